// round 10
// baseline (speedup 1.0000x reference)
#include <cuda_runtime.h>
#include <cuda_fp16.h>
#include <cstdint>
#include <math.h>

#define NE 8
#define NTOK 16384
#define DIM 1024
#define FF 2048
#define NKT1 (DIM / 64)
#define NKT2 (FF / 64)

// ---------------- scratch (device globals; no allocation) ----------------
__device__ int    g_counts[NE];
__device__ int    g_offsets[NE + 1];
__device__ int    g_tok[NE * NTOK];
__device__ float  g_cw[NE * NTOK];
__device__ __half g_H[(size_t)2 * NTOK * FF];        // hidden activations (fp16)
__device__ __half g_xh[(size_t)NTOK * DIM];          // fp16 x
__device__ __half g_w1h[(size_t)NE * FF * DIM];      // fp16 w1
__device__ __half g_w2h[(size_t)NE * DIM * FF];      // fp16 w2
__device__ __half g_w3h[(size_t)NE * FF * DIM];      // fp16 w3

// ---------------- helpers ----------------
__device__ __forceinline__ uint32_t ph2(float a, float b) {
    __half2 h = __floats2half2_rn(a, b);
    return *(uint32_t*)&h;
}

static __device__ __forceinline__ uint32_t smem_u32(const void* p) {
    uint32_t a;
    asm("{ .reg .u64 t; cvta.to.shared.u64 t, %1; cvt.u32.u64 %0, t; }" : "=r"(a) : "l"(p));
    return a;
}

__device__ __forceinline__ void mma16(float* c, const uint32_t* a, const uint32_t* b) {
    asm volatile(
        "mma.sync.aligned.m16n8k16.row.col.f32.f16.f16.f32 "
        "{%0,%1,%2,%3},{%4,%5,%6,%7},{%8,%9},{%0,%1,%2,%3};"
        : "+f"(c[0]), "+f"(c[1]), "+f"(c[2]), "+f"(c[3])
        : "r"(a[0]), "r"(a[1]), "r"(a[2]), "r"(a[3]), "r"(b[0]), "r"(b[1]));
}

#define LDSM4(r0_, r1_, r2_, r3_, addr)                                        \
    asm volatile("ldmatrix.sync.aligned.m8n8.x4.shared.b16 {%0,%1,%2,%3}, [%4];" \
        : "=r"(r0_), "=r"(r1_), "=r"(r2_), "=r"(r3_) : "r"(addr))

__device__ __forceinline__ void cpa16(uint32_t dst, const void* src, uint32_t nbytes) {
    asm volatile("cp.async.cg.shared.global [%0], [%1], 16, %2;"
                 :: "r"(dst), "l"(src), "r"(nbytes) : "memory");
}
#define CP_COMMIT() asm volatile("cp.async.commit_group;" ::: "memory")
#define CP_WAIT1()  asm volatile("cp.async.wait_group 1;" ::: "memory")

// 128B-row swizzle (64 halfs/row): row r, 16B chunk c (0..7) -> phys chunk c^(r&7).
__device__ __forceinline__ uint32_t swb32(int r, int c) {
    return (uint32_t)(r * 128 + ((c ^ r) & 7) * 16);
}

// ---------------- prepass: fp32 -> fp16, 8 floats/thread ----------------
__global__ void tohalf_kernel(const float* __restrict__ src, __half* __restrict__ dst, int n8) {
    int i = blockIdx.x * blockDim.x + threadIdx.x;
    if (i < n8) {
        float4 a = ((const float4*)src)[2 * i];
        float4 b = ((const float4*)src)[2 * i + 1];
        uint4 u;
        u.x = ph2(a.x, a.y); u.y = ph2(a.z, a.w);
        u.z = ph2(b.x, b.y); u.w = ph2(b.z, b.w);
        ((uint4*)dst)[i] = u;
    }
}

// ---------------- kernel 0: zero output (float4) + counts ----------------
__global__ void zero_kernel(float4* out, int n4) {
    int i = blockIdx.x * blockDim.x + threadIdx.x;
    if (i < n4) out[i] = make_float4(0.f, 0.f, 0.f, 0.f);
    if (blockIdx.x == 0 && threadIdx.x < NE) g_counts[threadIdx.x] = 0;
}

// ---------------- kernel 1: gating + routing (one warp per token) ----------------
__global__ void gate_kernel(const float* __restrict__ x, const float* __restrict__ gw) {
    int warp = threadIdx.x >> 5;
    int lane = threadIdx.x & 31;
    int token = blockIdx.x * 8 + warp;

    const float* xr = x + (size_t)token * DIM;
    float xv[32];
#pragma unroll
    for (int j = 0; j < 32; j++) xv[j] = xr[j * 32 + lane];

    float logits[NE];
#pragma unroll
    for (int e = 0; e < NE; e++) {
        const float* g = gw + e * DIM;
        float s = 0.0f;
#pragma unroll
        for (int j = 0; j < 32; j++) s += xv[j] * g[j * 32 + lane];
#pragma unroll
        for (int o = 16; o; o >>= 1) s += __shfl_xor_sync(0xffffffffu, s, o);
        logits[e] = s;
    }

    if (lane == 0) {
        int i1 = 0;
#pragma unroll
        for (int e = 1; e < NE; e++)
            if (logits[e] > logits[i1]) i1 = e;
        int i2 = -1;
#pragma unroll
        for (int e = 0; e < NE; e++) {
            if (e == i1) continue;
            if (i2 < 0 || logits[e] > logits[i2]) i2 = e;
        }
        float p1 = 1.0f / (1.0f + __expf(logits[i2] - logits[i1]));
        float p2 = 1.0f - p1;
        int s1 = atomicAdd(&g_counts[i1], 1);
        g_tok[i1 * NTOK + s1] = token;
        g_cw[i1 * NTOK + s1]  = p1;
        int s2 = atomicAdd(&g_counts[i2], 1);
        g_tok[i2 * NTOK + s2] = token;
        g_cw[i2 * NTOK + s2]  = p2;
    }
}

// ---------------- kernel 2: prefix over 8 counts ----------------
__global__ void prefix_kernel() {
    if (threadIdx.x == 0) {
        int a = 0;
        for (int e = 0; e < NE; e++) { g_offsets[e] = a; a += g_counts[e]; }
        g_offsets[NE] = a;
    }
}

// ---------------- tile scheduler ----------------
__device__ __forceinline__ bool find_tile(int bx, int& e, int& tile, int& cnt) {
    int acc = 0;
    e = -1;
#pragma unroll
    for (int ee = 0; ee < NE; ee++) {
        int c = g_counts[ee];
        int t = (c + 127) >> 7;
        if (e < 0 && bx < acc + t) { e = ee; tile = bx - acc; cnt = c; }
        acc += t;
    }
    return e >= 0;
}

// dynamic SMEM: [0:512) stok, [512:1024) scw, stages at 1024 + s*32768
#define STG_BASE 1024
#define STG_SZ   32768
#define SMEM_BYTES (STG_BASE + 3 * STG_SZ)

// ---------------- kernel 3: GEMM1 (x@w1^T, x@w3^T) -> silu*mul -> H(fp16) ----------------
// grid = (n_tiles, m_tiles): n fastest -> n-tiles sharing an m-tile run concurrently (L2 reuse)
__global__ __launch_bounds__(128, 2) void gemm1_kernel() {
    extern __shared__ char dsm[];
    int e, tile, cnt;
    if (!find_tile(blockIdx.y, e, tile, cnt)) return;
    int offs = g_offsets[e];
    int n0 = blockIdx.x * 64;

    int tid = threadIdx.x;
    int* stok = (int*)dsm;
    {
        int i = tile * 128 + tid;
        stok[tid] = (i < cnt) ? g_tok[e * NTOK + i] : -1;
    }
    __syncthreads();

    int warp = tid >> 5, lane = tid & 31;
    int wm = warp >> 1, wn = warp & 1;
    uint32_t sb = smem_u32(dsm);

    // ---- cp.async assignments: A 128x8 chunks (8/thr), B1/B3 64x8 (4/thr each) ----
    const __half* asrc[8]; uint32_t asz[8], adst[8];
#pragma unroll
    for (int j = 0; j < 8; j++) {
        int idx = tid + j * 128;
        int r = idx >> 3, c = idx & 7;
        int t = stok[r];
        asrc[j] = g_xh + (size_t)(t < 0 ? 0 : t) * DIM + c * 8;
        asz[j]  = (t < 0) ? 0u : 16u;
        adst[j] = swb32(r, c);
    }
    const __half* b1src[4]; const __half* b3src[4]; uint32_t bdst[4];
#pragma unroll
    for (int j = 0; j < 4; j++) {
        int idx = tid + j * 128;
        int r = idx >> 3, c = idx & 7;
        b1src[j] = g_w1h + (size_t)e * FF * DIM + (size_t)(n0 + r) * DIM + c * 8;
        b3src[j] = g_w3h + (size_t)e * FF * DIM + (size_t)(n0 + r) * DIM + c * 8;
        bdst[j]  = swb32(r, c);
    }
    auto issue_stage = [&](int s, int kt) {
        uint32_t base = sb + STG_BASE + s * STG_SZ;
        int k0 = kt * 64;
#pragma unroll
        for (int j = 0; j < 8; j++) cpa16(base + adst[j], asrc[j] + k0, asz[j]);
#pragma unroll
        for (int j = 0; j < 4; j++) cpa16(base + 16384 + bdst[j], b1src[j] + k0, 16);
#pragma unroll
        for (int j = 0; j < 4; j++) cpa16(base + 24576 + bdst[j], b3src[j] + k0, 16);
    };

    // ---- ldmatrix fragment offsets ----
    int arow = (((lane >> 3) & 1) << 3) + (lane & 7);
    int acol = lane >> 4;
    int brow = (((lane >> 4) & 1) << 3) + (lane & 7);
    int bcol = (lane >> 3) & 1;
    uint32_t offA[4][4], offB[2][4];
#pragma unroll
    for (int mt = 0; mt < 4; mt++)
#pragma unroll
        for (int kki = 0; kki < 4; kki++)
            offA[mt][kki] = swb32(wm * 64 + mt * 16 + arow, kki * 2 + acol);
#pragma unroll
    for (int p = 0; p < 2; p++)
#pragma unroll
        for (int kki = 0; kki < 4; kki++)
            offB[p][kki] = swb32(wn * 32 + p * 16 + brow, kki * 2 + bcol);

    float acc1[4][4][4] = {};
    float acc3[4][4][4] = {};

    auto compute_stage = [&](int s) {
        uint32_t base = sb + STG_BASE + s * STG_SZ;
        uint32_t aA = base, aB1 = base + 16384, aB3 = base + 24576;
#pragma unroll
        for (int kki = 0; kki < 4; kki++) {
            uint32_t a[4][4];
#pragma unroll
            for (int mt = 0; mt < 4; mt++)
                LDSM4(a[mt][0], a[mt][1], a[mt][2], a[mt][3], aA + offA[mt][kki]);
#pragma unroll
            for (int p = 0; p < 2; p++) {
                uint32_t b1[4], b3[4];
                LDSM4(b1[0], b1[1], b1[2], b1[3], aB1 + offB[p][kki]);
                LDSM4(b3[0], b3[1], b3[2], b3[3], aB3 + offB[p][kki]);
#pragma unroll
                for (int mt = 0; mt < 4; mt++) {
                    mma16(acc1[mt][2 * p],     a[mt], &b1[0]);
                    mma16(acc1[mt][2 * p + 1], a[mt], &b1[2]);
                    mma16(acc3[mt][2 * p],     a[mt], &b3[0]);
                    mma16(acc3[mt][2 * p + 1], a[mt], &b3[2]);
                }
            }
        }
    };

    issue_stage(0, 0); CP_COMMIT();
    issue_stage(1, 1); CP_COMMIT();
#pragma unroll 1
    for (int kt = 0; kt < NKT1; kt++) {
        CP_WAIT1();
        __syncthreads();
        compute_stage(kt % 3);
        if (kt + 2 < NKT1) issue_stage((kt + 2) % 3, kt + 2);
        CP_COMMIT();
    }

    // epilogue: h = silu(s1) * s3 -> g_H (fp16, half2 stores)
#pragma unroll
    for (int mt = 0; mt < 4; mt++) {
#pragma unroll
        for (int nt = 0; nt < 4; nt++) {
            int r0 = wm * 64 + mt * 16 + (lane >> 2);
            int cc = wn * 32 + nt * 8 + ((lane & 3) << 1);
#pragma unroll
            for (int h8 = 0; h8 < 2; h8++) {
                int i = tile * 128 + r0 + h8 * 8;
                if (i < cnt) {
                    float s1a = acc1[mt][nt][2 * h8],     s3a = acc3[mt][nt][2 * h8];
                    float s1b = acc1[mt][nt][2 * h8 + 1], s3b = acc3[mt][nt][2 * h8 + 1];
                    float ha = (s1a / (1.0f + __expf(-s1a))) * s3a;
                    float hb = (s1b / (1.0f + __expf(-s1b))) * s3b;
                    *(__half2*)(g_H + (size_t)(offs + i) * FF + n0 + cc) =
                        __floats2half2_rn(ha, hb);
                }
            }
        }
    }
}

// ---------------- kernel 4: GEMM2 (H @ w2^T), BN=128, scaled scatter-add ----------------
// grid = (n_tiles, m_tiles): the 8 n-tiles of an m-tile run concurrently -> H hits L2
__global__ __launch_bounds__(128, 2) void gemm2_kernel(float* __restrict__ out) {
    extern __shared__ char dsm[];
    int e, tile, cnt;
    if (!find_tile(blockIdx.y, e, tile, cnt)) return;
    int offs = g_offsets[e];
    int n0 = blockIdx.x * 128;

    int tid = threadIdx.x;
    int*   stok = (int*)dsm;
    float* scw  = (float*)(dsm + 512);
    {
        int i = tile * 128 + tid;
        stok[tid] = (i < cnt) ? g_tok[e * NTOK + i] : -1;
        scw[tid]  = (i < cnt) ? g_cw[e * NTOK + i] : 0.0f;
    }
    __syncthreads();

    int warp = tid >> 5, lane = tid & 31;
    int wm = warp >> 1, wn = warp & 1;
    uint32_t sb = smem_u32(dsm);

    const __half* asrc[8]; uint32_t asz[8], adst[8];
    const __half* bsrc[8];
#pragma unroll
    for (int j = 0; j < 8; j++) {
        int idx = tid + j * 128;
        int r = idx >> 3, c = idx & 7;
        bool av = (tile * 128 + r) < cnt;
        asrc[j] = g_H + (size_t)(offs + tile * 128 + (av ? r : 0)) * FF + c * 8;
        asz[j]  = av ? 16u : 0u;
        adst[j] = swb32(r, c);
        bsrc[j] = g_w2h + (size_t)e * DIM * FF + (size_t)(n0 + r) * FF + c * 8;
    }
    auto issue_stage = [&](int s, int kt) {
        uint32_t base = sb + STG_BASE + s * STG_SZ;
        int k0 = kt * 64;
#pragma unroll
        for (int j = 0; j < 8; j++) cpa16(base + adst[j], asrc[j] + k0, asz[j]);
#pragma unroll
        for (int j = 0; j < 8; j++) cpa16(base + 16384 + adst[j], bsrc[j] + k0, 16);
    };

    int arow = (((lane >> 3) & 1) << 3) + (lane & 7);
    int acol = lane >> 4;
    int brow = (((lane >> 4) & 1) << 3) + (lane & 7);
    int bcol = (lane >> 3) & 1;
    uint32_t offA[4][4], offB[4][4];
#pragma unroll
    for (int mt = 0; mt < 4; mt++)
#pragma unroll
        for (int kki = 0; kki < 4; kki++)
            offA[mt][kki] = swb32(wm * 64 + mt * 16 + arow, kki * 2 + acol);
#pragma unroll
    for (int p = 0; p < 4; p++)
#pragma unroll
        for (int kki = 0; kki < 4; kki++)
            offB[p][kki] = swb32(wn * 64 + p * 16 + brow, kki * 2 + bcol);

    float acc[4][8][4] = {};

    auto compute_stage = [&](int s) {
        uint32_t base = sb + STG_BASE + s * STG_SZ;
        uint32_t aA = base, aB = base + 16384;
#pragma unroll
        for (int kki = 0; kki < 4; kki++) {
            uint32_t a[4][4];
#pragma unroll
            for (int mt = 0; mt < 4; mt++)
                LDSM4(a[mt][0], a[mt][1], a[mt][2], a[mt][3], aA + offA[mt][kki]);
#pragma unroll
            for (int p = 0; p < 4; p++) {
                uint32_t b[4];
                LDSM4(b[0], b[1], b[2], b[3], aB + offB[p][kki]);
#pragma unroll
                for (int mt = 0; mt < 4; mt++) {
                    mma16(acc[mt][2 * p],     a[mt], &b[0]);
                    mma16(acc[mt][2 * p + 1], a[mt], &b[2]);
                }
            }
        }
    };

    issue_stage(0, 0); CP_COMMIT();
    issue_stage(1, 1); CP_COMMIT();
#pragma unroll 1
    for (int kt = 0; kt < NKT2; kt++) {
        CP_WAIT1();
        __syncthreads();
        compute_stage(kt % 3);
        if (kt + 2 < NKT2) issue_stage((kt + 2) % 3, kt + 2);
        CP_COMMIT();
    }

    // epilogue: out[token, n] += cw * acc  (2 commutative adds/elem -> deterministic)
#pragma unroll
    for (int mt = 0; mt < 4; mt++) {
#pragma unroll
        for (int nt = 0; nt < 8; nt++) {
#pragma unroll
            for (int q = 0; q < 4; q++) {
                int r  = wm * 64 + mt * 16 + (lane >> 2) + ((q >= 2) ? 8 : 0);
                int cc = wn * 64 + nt * 8 + ((lane & 3) << 1) + (q & 1);
                int i = tile * 128 + r;
                if (i < cnt) {
                    int t  = stok[r];
                    float w = scw[r];
                    atomicAdd(&out[(size_t)t * DIM + n0 + cc], acc[mt][nt][q] * w);
                }
            }
        }
    }
}

// ---------------- launch ----------------
extern "C" void kernel_launch(void* const* d_in, const int* in_sizes, int n_in,
                              void* d_out, int out_size) {
    const float* x  = (const float*)d_in[0];
    const float* gw = (const float*)d_in[1];
    const float* w1 = (const float*)d_in[2];
    const float* w2 = (const float*)d_in[3];
    const float* w3 = (const float*)d_in[4];
    float* out = (float*)d_out;

    cudaFuncSetAttribute(gemm1_kernel, cudaFuncAttributeMaxDynamicSharedMemorySize, SMEM_BYTES);
    cudaFuncSetAttribute(gemm2_kernel, cudaFuncAttributeMaxDynamicSharedMemorySize, SMEM_BYTES);

    __half *xh, *w1h, *w2h, *w3h;
    cudaGetSymbolAddress((void**)&xh,  g_xh);
    cudaGetSymbolAddress((void**)&w1h, g_w1h);
    cudaGetSymbolAddress((void**)&w2h, g_w2h);
    cudaGetSymbolAddress((void**)&w3h, g_w3h);

    int nx8 = NTOK * DIM / 8;
    int nw8 = NE * FF * DIM / 8;
    tohalf_kernel<<<(nx8 + 255) / 256, 256>>>(x, xh, nx8);
    tohalf_kernel<<<(nw8 + 255) / 256, 256>>>(w1, w1h, nw8);
    tohalf_kernel<<<(nw8 + 255) / 256, 256>>>(w2, w2h, nw8);
    tohalf_kernel<<<(nw8 + 255) / 256, 256>>>(w3, w3h, nw8);

    zero_kernel<<<(out_size / 4 + 255) / 256, 256>>>((float4*)out, out_size / 4);
    gate_kernel<<<NTOK / 8, 256>>>(x, gw);
    prefix_kernel<<<1, 32>>>();
    gemm1_kernel<<<dim3(FF / 64, 264), 128, SMEM_BYTES>>>();
    gemm2_kernel<<<dim3(DIM / 128, 264), 128, SMEM_BYTES>>>(out);
}

// round 11
// speedup vs baseline: 1.4552x; 1.4552x over previous
#include <cuda_runtime.h>
#include <cuda_fp16.h>
#include <cstdint>
#include <math.h>

#define NE 8
#define NTOK 16384
#define DIM 1024
#define FF 2048
#define NKT1 (DIM / 64)
#define NKT2 (FF / 64)

// ---------------- scratch (device globals; no allocation) ----------------
__device__ int    g_counts[NE];
__device__ int    g_offsets[NE + 1];
__device__ int    g_tok[NE * NTOK];
__device__ float  g_cw[NE * NTOK];
__device__ int    g_sE[2 * NTOK];                    // per-token expert of slot 0/1
__device__ int    g_sP[2 * NTOK];                    // per-token position within expert bucket
__device__ __half g_H[(size_t)2 * NTOK * FF];        // hidden activations (fp16)
__device__ float  g_O[(size_t)2 * NTOK * DIM];       // per-slot scaled expert outputs (fp32)
__device__ __half g_xh[(size_t)NTOK * DIM];          // fp16 x
__device__ __half g_w1h[(size_t)NE * FF * DIM];      // fp16 w1
__device__ __half g_w2h[(size_t)NE * DIM * FF];      // fp16 w2
__device__ __half g_w3h[(size_t)NE * FF * DIM];      // fp16 w3

// ---------------- helpers ----------------
__device__ __forceinline__ uint32_t ph2(float a, float b) {
    __half2 h = __floats2half2_rn(a, b);
    return *(uint32_t*)&h;
}

static __device__ __forceinline__ uint32_t smem_u32(const void* p) {
    uint32_t a;
    asm("{ .reg .u64 t; cvta.to.shared.u64 t, %1; cvt.u32.u64 %0, t; }" : "=r"(a) : "l"(p));
    return a;
}

__device__ __forceinline__ void mma16(float* c, const uint32_t* a, const uint32_t* b) {
    asm volatile(
        "mma.sync.aligned.m16n8k16.row.col.f32.f16.f16.f32 "
        "{%0,%1,%2,%3},{%4,%5,%6,%7},{%8,%9},{%0,%1,%2,%3};"
        : "+f"(c[0]), "+f"(c[1]), "+f"(c[2]), "+f"(c[3])
        : "r"(a[0]), "r"(a[1]), "r"(a[2]), "r"(a[3]), "r"(b[0]), "r"(b[1]));
}

#define LDSM4(r0_, r1_, r2_, r3_, addr)                                        \
    asm volatile("ldmatrix.sync.aligned.m8n8.x4.shared.b16 {%0,%1,%2,%3}, [%4];" \
        : "=r"(r0_), "=r"(r1_), "=r"(r2_), "=r"(r3_) : "r"(addr))

__device__ __forceinline__ void cpa16(uint32_t dst, const void* src, uint32_t nbytes) {
    asm volatile("cp.async.cg.shared.global [%0], [%1], 16, %2;"
                 :: "r"(dst), "l"(src), "r"(nbytes) : "memory");
}
#define CP_COMMIT() asm volatile("cp.async.commit_group;" ::: "memory")
#define CP_WAIT1()  asm volatile("cp.async.wait_group 1;" ::: "memory")

// 128B-row swizzle (64 halfs/row): row r, 16B chunk c (0..7) -> phys chunk c^(r&7).
__device__ __forceinline__ uint32_t swb32(int r, int c) {
    return (uint32_t)(r * 128 + ((c ^ r) & 7) * 16);
}

// ---------------- prepass: fp32 -> fp16, 8 floats/thread ----------------
__global__ void tohalf_kernel(const float* __restrict__ src, __half* __restrict__ dst, int n8) {
    int i = blockIdx.x * blockDim.x + threadIdx.x;
    if (i < n8) {
        float4 a = ((const float4*)src)[2 * i];
        float4 b = ((const float4*)src)[2 * i + 1];
        uint4 u;
        u.x = ph2(a.x, a.y); u.y = ph2(a.z, a.w);
        u.z = ph2(b.x, b.y); u.w = ph2(b.z, b.w);
        ((uint4*)dst)[i] = u;
    }
}

// ---------------- kernel 0: init counts ----------------
__global__ void init_kernel() {
    if (threadIdx.x < NE) g_counts[threadIdx.x] = 0;
}

// ---------------- kernel 1: gating + routing (one warp per token) ----------------
__global__ void gate_kernel(const float* __restrict__ x, const float* __restrict__ gw) {
    int warp = threadIdx.x >> 5;
    int lane = threadIdx.x & 31;
    int token = blockIdx.x * 8 + warp;

    const float* xr = x + (size_t)token * DIM;
    float xv[32];
#pragma unroll
    for (int j = 0; j < 32; j++) xv[j] = xr[j * 32 + lane];

    float logits[NE];
#pragma unroll
    for (int e = 0; e < NE; e++) {
        const float* g = gw + e * DIM;
        float s = 0.0f;
#pragma unroll
        for (int j = 0; j < 32; j++) s += xv[j] * g[j * 32 + lane];
#pragma unroll
        for (int o = 16; o; o >>= 1) s += __shfl_xor_sync(0xffffffffu, s, o);
        logits[e] = s;
    }

    if (lane == 0) {
        int i1 = 0;
#pragma unroll
        for (int e = 1; e < NE; e++)
            if (logits[e] > logits[i1]) i1 = e;
        int i2 = -1;
#pragma unroll
        for (int e = 0; e < NE; e++) {
            if (e == i1) continue;
            if (i2 < 0 || logits[e] > logits[i2]) i2 = e;
        }
        float p1 = 1.0f / (1.0f + __expf(logits[i2] - logits[i1]));
        float p2 = 1.0f - p1;
        int s1 = atomicAdd(&g_counts[i1], 1);
        g_tok[i1 * NTOK + s1] = token;
        g_cw[i1 * NTOK + s1]  = p1;
        int s2 = atomicAdd(&g_counts[i2], 1);
        g_tok[i2 * NTOK + s2] = token;
        g_cw[i2 * NTOK + s2]  = p2;
        g_sE[2 * token] = i1;  g_sP[2 * token] = s1;
        g_sE[2 * token + 1] = i2;  g_sP[2 * token + 1] = s2;
    }
}

// ---------------- kernel 2: prefix over 8 counts ----------------
__global__ void prefix_kernel() {
    if (threadIdx.x == 0) {
        int a = 0;
        for (int e = 0; e < NE; e++) { g_offsets[e] = a; a += g_counts[e]; }
        g_offsets[NE] = a;
    }
}

// ---------------- tile scheduler ----------------
__device__ __forceinline__ bool find_tile(int bx, int& e, int& tile, int& cnt) {
    int acc = 0;
    e = -1;
#pragma unroll
    for (int ee = 0; ee < NE; ee++) {
        int c = g_counts[ee];
        int t = (c + 127) >> 7;
        if (e < 0 && bx < acc + t) { e = ee; tile = bx - acc; cnt = c; }
        acc += t;
    }
    return e >= 0;
}

// dynamic SMEM: [0:512) stok, [512:1024) scw, stages at 1024 + s*32768
#define STG_BASE 1024
#define STG_SZ   32768
#define SMEM_BYTES (STG_BASE + 3 * STG_SZ)

// ---------------- kernel 3: GEMM1 (x@w1^T, x@w3^T) -> silu*mul -> H(fp16) ----------------
// R9 grid layout: tile-id = blockIdx.x (fastest, 264-wide wave -> B n-slice L2 reuse)
__global__ __launch_bounds__(128, 2) void gemm1_kernel() {
    extern __shared__ char dsm[];
    int e, tile, cnt;
    if (!find_tile(blockIdx.x, e, tile, cnt)) return;
    int offs = g_offsets[e];
    int n0 = blockIdx.y * 64;

    int tid = threadIdx.x;
    int* stok = (int*)dsm;
    {
        int i = tile * 128 + tid;
        stok[tid] = (i < cnt) ? g_tok[e * NTOK + i] : -1;
    }
    __syncthreads();

    int warp = tid >> 5, lane = tid & 31;
    int wm = warp >> 1, wn = warp & 1;
    uint32_t sb = smem_u32(dsm);

    // ---- cp.async assignments: A 128x8 chunks (8/thr), B1/B3 64x8 (4/thr each) ----
    const __half* asrc[8]; uint32_t asz[8], adst[8];
#pragma unroll
    for (int j = 0; j < 8; j++) {
        int idx = tid + j * 128;
        int r = idx >> 3, c = idx & 7;
        int t = stok[r];
        asrc[j] = g_xh + (size_t)(t < 0 ? 0 : t) * DIM + c * 8;
        asz[j]  = (t < 0) ? 0u : 16u;
        adst[j] = swb32(r, c);
    }
    const __half* b1src[4]; const __half* b3src[4]; uint32_t bdst[4];
#pragma unroll
    for (int j = 0; j < 4; j++) {
        int idx = tid + j * 128;
        int r = idx >> 3, c = idx & 7;
        b1src[j] = g_w1h + (size_t)e * FF * DIM + (size_t)(n0 + r) * DIM + c * 8;
        b3src[j] = g_w3h + (size_t)e * FF * DIM + (size_t)(n0 + r) * DIM + c * 8;
        bdst[j]  = swb32(r, c);
    }
    auto issue_stage = [&](int s, int kt) {
        uint32_t base = sb + STG_BASE + s * STG_SZ;
        int k0 = kt * 64;
#pragma unroll
        for (int j = 0; j < 8; j++) cpa16(base + adst[j], asrc[j] + k0, asz[j]);
#pragma unroll
        for (int j = 0; j < 4; j++) cpa16(base + 16384 + bdst[j], b1src[j] + k0, 16);
#pragma unroll
        for (int j = 0; j < 4; j++) cpa16(base + 24576 + bdst[j], b3src[j] + k0, 16);
    };

    // ---- ldmatrix fragment offsets ----
    int arow = (((lane >> 3) & 1) << 3) + (lane & 7);
    int acol = lane >> 4;
    int brow = (((lane >> 4) & 1) << 3) + (lane & 7);
    int bcol = (lane >> 3) & 1;
    uint32_t offA[4][4], offB[2][4];
#pragma unroll
    for (int mt = 0; mt < 4; mt++)
#pragma unroll
        for (int kki = 0; kki < 4; kki++)
            offA[mt][kki] = swb32(wm * 64 + mt * 16 + arow, kki * 2 + acol);
#pragma unroll
    for (int p = 0; p < 2; p++)
#pragma unroll
        for (int kki = 0; kki < 4; kki++)
            offB[p][kki] = swb32(wn * 32 + p * 16 + brow, kki * 2 + bcol);

    float acc1[4][4][4] = {};
    float acc3[4][4][4] = {};

    auto compute_stage = [&](int s) {
        uint32_t base = sb + STG_BASE + s * STG_SZ;
        uint32_t aA = base, aB1 = base + 16384, aB3 = base + 24576;
#pragma unroll
        for (int kki = 0; kki < 4; kki++) {
            uint32_t a[4][4];
#pragma unroll
            for (int mt = 0; mt < 4; mt++)
                LDSM4(a[mt][0], a[mt][1], a[mt][2], a[mt][3], aA + offA[mt][kki]);
#pragma unroll
            for (int p = 0; p < 2; p++) {
                uint32_t b1[4], b3[4];
                LDSM4(b1[0], b1[1], b1[2], b1[3], aB1 + offB[p][kki]);
                LDSM4(b3[0], b3[1], b3[2], b3[3], aB3 + offB[p][kki]);
#pragma unroll
                for (int mt = 0; mt < 4; mt++) {
                    mma16(acc1[mt][2 * p],     a[mt], &b1[0]);
                    mma16(acc1[mt][2 * p + 1], a[mt], &b1[2]);
                    mma16(acc3[mt][2 * p],     a[mt], &b3[0]);
                    mma16(acc3[mt][2 * p + 1], a[mt], &b3[2]);
                }
            }
        }
    };

    issue_stage(0, 0); CP_COMMIT();
    issue_stage(1, 1); CP_COMMIT();
#pragma unroll 1
    for (int kt = 0; kt < NKT1; kt++) {
        CP_WAIT1();
        __syncthreads();
        compute_stage(kt % 3);
        if (kt + 2 < NKT1) issue_stage((kt + 2) % 3, kt + 2);
        CP_COMMIT();
    }

    // epilogue: h = silu(s1) * s3 -> g_H (fp16, half2 stores)
#pragma unroll
    for (int mt = 0; mt < 4; mt++) {
#pragma unroll
        for (int nt = 0; nt < 4; nt++) {
            int r0 = wm * 64 + mt * 16 + (lane >> 2);
            int cc = wn * 32 + nt * 8 + ((lane & 3) << 1);
#pragma unroll
            for (int h8 = 0; h8 < 2; h8++) {
                int i = tile * 128 + r0 + h8 * 8;
                if (i < cnt) {
                    float s1a = acc1[mt][nt][2 * h8],     s3a = acc3[mt][nt][2 * h8];
                    float s1b = acc1[mt][nt][2 * h8 + 1], s3b = acc3[mt][nt][2 * h8 + 1];
                    float ha = (s1a / (1.0f + __expf(-s1a))) * s3a;
                    float hb = (s1b / (1.0f + __expf(-s1b))) * s3b;
                    *(__half2*)(g_H + (size_t)(offs + i) * FF + n0 + cc) =
                        __floats2half2_rn(ha, hb);
                }
            }
        }
    }
}

// ---------------- kernel 4: GEMM2 (H @ w2^T), scaled rows -> g_O (no atomics) ----------------
__global__ __launch_bounds__(128, 2) void gemm2_kernel() {
    extern __shared__ char dsm[];
    int e, tile, cnt;
    if (!find_tile(blockIdx.x, e, tile, cnt)) return;
    int offs = g_offsets[e];
    int n0 = blockIdx.y * 128;

    int tid = threadIdx.x;
    float* scw = (float*)(dsm + 512);
    {
        int i = tile * 128 + tid;
        scw[tid] = (i < cnt) ? g_cw[e * NTOK + i] : 0.0f;
    }
    __syncthreads();

    int warp = tid >> 5, lane = tid & 31;
    int wm = warp >> 1, wn = warp & 1;
    uint32_t sb = smem_u32(dsm);

    const __half* asrc[8]; uint32_t asz[8], adst[8];
    const __half* bsrc[8];
#pragma unroll
    for (int j = 0; j < 8; j++) {
        int idx = tid + j * 128;
        int r = idx >> 3, c = idx & 7;
        bool av = (tile * 128 + r) < cnt;
        asrc[j] = g_H + (size_t)(offs + tile * 128 + (av ? r : 0)) * FF + c * 8;
        asz[j]  = av ? 16u : 0u;
        adst[j] = swb32(r, c);
        bsrc[j] = g_w2h + (size_t)e * DIM * FF + (size_t)(n0 + r) * FF + c * 8;
    }
    auto issue_stage = [&](int s, int kt) {
        uint32_t base = sb + STG_BASE + s * STG_SZ;
        int k0 = kt * 64;
#pragma unroll
        for (int j = 0; j < 8; j++) cpa16(base + adst[j], asrc[j] + k0, asz[j]);
#pragma unroll
        for (int j = 0; j < 8; j++) cpa16(base + 16384 + adst[j], bsrc[j] + k0, 16);
    };

    int arow = (((lane >> 3) & 1) << 3) + (lane & 7);
    int acol = lane >> 4;
    int brow = (((lane >> 4) & 1) << 3) + (lane & 7);
    int bcol = (lane >> 3) & 1;
    uint32_t offA[4][4], offB[4][4];
#pragma unroll
    for (int mt = 0; mt < 4; mt++)
#pragma unroll
        for (int kki = 0; kki < 4; kki++)
            offA[mt][kki] = swb32(wm * 64 + mt * 16 + arow, kki * 2 + acol);
#pragma unroll
    for (int p = 0; p < 4; p++)
#pragma unroll
        for (int kki = 0; kki < 4; kki++)
            offB[p][kki] = swb32(wn * 64 + p * 16 + brow, kki * 2 + bcol);

    float acc[4][8][4] = {};

    auto compute_stage = [&](int s) {
        uint32_t base = sb + STG_BASE + s * STG_SZ;
        uint32_t aA = base, aB = base + 16384;
#pragma unroll
        for (int kki = 0; kki < 4; kki++) {
            uint32_t a[4][4];
#pragma unroll
            for (int mt = 0; mt < 4; mt++)
                LDSM4(a[mt][0], a[mt][1], a[mt][2], a[mt][3], aA + offA[mt][kki]);
#pragma unroll
            for (int p = 0; p < 4; p++) {
                uint32_t b[4];
                LDSM4(b[0], b[1], b[2], b[3], aB + offB[p][kki]);
#pragma unroll
                for (int mt = 0; mt < 4; mt++) {
                    mma16(acc[mt][2 * p],     a[mt], &b[0]);
                    mma16(acc[mt][2 * p + 1], a[mt], &b[2]);
                }
            }
        }
    };

    issue_stage(0, 0); CP_COMMIT();
    issue_stage(1, 1); CP_COMMIT();
#pragma unroll 1
    for (int kt = 0; kt < NKT2; kt++) {
        CP_WAIT1();
        __syncthreads();
        compute_stage(kt % 3);
        if (kt + 2 < NKT2) issue_stage((kt + 2) % 3, kt + 2);
        CP_COMMIT();
    }

    // epilogue: g_O[slot row] = cw * acc  (plain stores, float2)
#pragma unroll
    for (int mt = 0; mt < 4; mt++) {
#pragma unroll
        for (int nt = 0; nt < 8; nt++) {
            int r0 = wm * 64 + mt * 16 + (lane >> 2);
            int cc = wn * 64 + nt * 8 + ((lane & 3) << 1);
#pragma unroll
            for (int h8 = 0; h8 < 2; h8++) {
                int r = r0 + h8 * 8;
                int i = tile * 128 + r;
                if (i < cnt) {
                    float w = scw[r];
                    float2 v = make_float2(acc[mt][nt][2 * h8] * w,
                                           acc[mt][nt][2 * h8 + 1] * w);
                    *(float2*)(g_O + (size_t)(offs + i) * DIM + n0 + cc) = v;
                }
            }
        }
    }
}

// ---------------- kernel 5: combine (one block per token, write-once out) ----------------
__global__ __launch_bounds__(256) void combine_kernel(float4* __restrict__ out) {
    int t = blockIdx.x;
    int d = threadIdx.x;                       // 256 float4 = 1024 floats
    size_t r1 = (size_t)(g_offsets[g_sE[2 * t]]     + g_sP[2 * t]);
    size_t r2 = (size_t)(g_offsets[g_sE[2 * t + 1]] + g_sP[2 * t + 1]);
    float4 a = ((const float4*)(g_O + r1 * DIM))[d];
    float4 b = ((const float4*)(g_O + r2 * DIM))[d];
    out[(size_t)t * (DIM / 4) + d] =
        make_float4(a.x + b.x, a.y + b.y, a.z + b.z, a.w + b.w);
}

// ---------------- launch ----------------
extern "C" void kernel_launch(void* const* d_in, const int* in_sizes, int n_in,
                              void* d_out, int out_size) {
    const float* x  = (const float*)d_in[0];
    const float* gw = (const float*)d_in[1];
    const float* w1 = (const float*)d_in[2];
    const float* w2 = (const float*)d_in[3];
    const float* w3 = (const float*)d_in[4];
    float* out = (float*)d_out;

    cudaFuncSetAttribute(gemm1_kernel, cudaFuncAttributeMaxDynamicSharedMemorySize, SMEM_BYTES);
    cudaFuncSetAttribute(gemm2_kernel, cudaFuncAttributeMaxDynamicSharedMemorySize, SMEM_BYTES);

    __half *xh, *w1h, *w2h, *w3h;
    cudaGetSymbolAddress((void**)&xh,  g_xh);
    cudaGetSymbolAddress((void**)&w1h, g_w1h);
    cudaGetSymbolAddress((void**)&w2h, g_w2h);
    cudaGetSymbolAddress((void**)&w3h, g_w3h);

    int nx8 = NTOK * DIM / 8;
    int nw8 = NE * FF * DIM / 8;
    tohalf_kernel<<<(nx8 + 255) / 256, 256>>>(x, xh, nx8);
    tohalf_kernel<<<(nw8 + 255) / 256, 256>>>(w1, w1h, nw8);
    tohalf_kernel<<<(nw8 + 255) / 256, 256>>>(w2, w2h, nw8);
    tohalf_kernel<<<(nw8 + 255) / 256, 256>>>(w3, w3h, nw8);

    init_kernel<<<1, 32>>>();
    gate_kernel<<<NTOK / 8, 256>>>(x, gw);
    prefix_kernel<<<1, 32>>>();
    gemm1_kernel<<<dim3(264, FF / 64), 128, SMEM_BYTES>>>();
    gemm2_kernel<<<dim3(264, DIM / 128), 128, SMEM_BYTES>>>();
    combine_kernel<<<NTOK, 256>>>((float4*)out);
}

// round 15
// speedup vs baseline: 1.4929x; 1.0259x over previous
#include <cuda_runtime.h>
#include <cuda_fp16.h>
#include <cstdint>
#include <math.h>

#define NE 8
#define NTOK 16384
#define DIM 1024
#define FF 2048
#define NKT1 (DIM / 64)
#define NKT2 (FF / 64)

// ---------------- scratch (device globals; no allocation) ----------------
__device__ int    g_counts[NE];
__device__ int    g_tok[NE * NTOK];
__device__ float  g_cw[NE * NTOK];
__device__ int    g_sE[2 * NTOK];                    // per-token expert of slot 0/1
__device__ int    g_sP[2 * NTOK];                    // per-token position within expert bucket
__device__ __half g_H[(size_t)2 * NTOK * FF];        // hidden activations (fp16)
__device__ float  g_O[(size_t)2 * NTOK * DIM];       // per-slot scaled expert outputs (fp32)
__device__ __half g_xh[(size_t)NTOK * DIM];          // fp16 x
__device__ __half g_w1h[(size_t)NE * FF * DIM];      // fp16 w1
__device__ __half g_w2h[(size_t)NE * DIM * FF];      // fp16 w2
__device__ __half g_w3h[(size_t)NE * FF * DIM];      // fp16 w3

// ---------------- helpers ----------------
__device__ __forceinline__ uint32_t ph2(float a, float b) {
    __half2 h = __floats2half2_rn(a, b);
    return *(uint32_t*)&h;
}

static __device__ __forceinline__ uint32_t smem_u32(const void* p) {
    uint32_t a;
    asm("{ .reg .u64 t; cvta.to.shared.u64 t, %1; cvt.u32.u64 %0, t; }" : "=r"(a) : "l"(p));
    return a;
}

__device__ __forceinline__ void mma16(float* c, const uint32_t* a, const uint32_t* b) {
    asm volatile(
        "mma.sync.aligned.m16n8k16.row.col.f32.f16.f16.f32 "
        "{%0,%1,%2,%3},{%4,%5,%6,%7},{%8,%9},{%0,%1,%2,%3};"
        : "+f"(c[0]), "+f"(c[1]), "+f"(c[2]), "+f"(c[3])
        : "r"(a[0]), "r"(a[1]), "r"(a[2]), "r"(a[3]), "r"(b[0]), "r"(b[1]));
}

#define LDSM4(r0_, r1_, r2_, r3_, addr)                                        \
    asm volatile("ldmatrix.sync.aligned.m8n8.x4.shared.b16 {%0,%1,%2,%3}, [%4];" \
        : "=r"(r0_), "=r"(r1_), "=r"(r2_), "=r"(r3_) : "r"(addr))

__device__ __forceinline__ void cpa16(uint32_t dst, const void* src, uint32_t nbytes) {
    asm volatile("cp.async.cg.shared.global [%0], [%1], 16, %2;"
                 :: "r"(dst), "l"(src), "r"(nbytes) : "memory");
}
#define CP_COMMIT() asm volatile("cp.async.commit_group;" ::: "memory")
#define CP_WAIT1()  asm volatile("cp.async.wait_group 1;" ::: "memory")

// 128B-row swizzle (64 halfs/row): row r, 16B chunk c (0..7) -> phys chunk c^(r&7).
__device__ __forceinline__ uint32_t swb32(int r, int c) {
    return (uint32_t)(r * 128 + ((c ^ r) & 7) * 16);
}

// ---------------- prepass: fp32 -> fp16, 8 floats/thread ----------------
__global__ void tohalf_kernel(const float* __restrict__ src, __half* __restrict__ dst, int n8) {
    int i = blockIdx.x * blockDim.x + threadIdx.x;
    if (i < n8) {
        float4 a = ((const float4*)src)[2 * i];
        float4 b = ((const float4*)src)[2 * i + 1];
        uint4 u;
        u.x = ph2(a.x, a.y); u.y = ph2(a.z, a.w);
        u.z = ph2(b.x, b.y); u.w = ph2(b.z, b.w);
        ((uint4*)dst)[i] = u;
    }
}

// ---------------- kernel 0: init counts ----------------
__global__ void init_kernel() {
    if (threadIdx.x < NE) g_counts[threadIdx.x] = 0;
}

// ---------------- kernel 1: gating + routing + x->fp16 (one warp per token) ----------------
__global__ void gate_kernel(const float* __restrict__ x, const float* __restrict__ gw) {
    int warp = threadIdx.x >> 5;
    int lane = threadIdx.x & 31;
    int token = blockIdx.x * 8 + warp;

    const float* xr = x + (size_t)token * DIM;
    float xv[32];
#pragma unroll
    for (int j = 0; j < 32; j++) xv[j] = xr[j * 32 + lane];

    // fused fp16 conversion of x (same __float2half_rn rounding as tohalf)
    __half* xh = g_xh + (size_t)token * DIM;
#pragma unroll
    for (int j = 0; j < 32; j++) xh[j * 32 + lane] = __float2half_rn(xv[j]);

    float logits[NE];
#pragma unroll
    for (int e = 0; e < NE; e++) {
        const float* g = gw + e * DIM;
        float s = 0.0f;
#pragma unroll
        for (int j = 0; j < 32; j++) s += xv[j] * g[j * 32 + lane];
#pragma unroll
        for (int o = 16; o; o >>= 1) s += __shfl_xor_sync(0xffffffffu, s, o);
        logits[e] = s;
    }

    if (lane == 0) {
        int i1 = 0;
#pragma unroll
        for (int e = 1; e < NE; e++)
            if (logits[e] > logits[i1]) i1 = e;
        int i2 = -1;
#pragma unroll
        for (int e = 0; e < NE; e++) {
            if (e == i1) continue;
            if (i2 < 0 || logits[e] > logits[i2]) i2 = e;
        }
        float p1 = 1.0f / (1.0f + __expf(logits[i2] - logits[i1]));
        float p2 = 1.0f - p1;
        int s1 = atomicAdd(&g_counts[i1], 1);
        g_tok[i1 * NTOK + s1] = token;
        g_cw[i1 * NTOK + s1]  = p1;
        int s2 = atomicAdd(&g_counts[i2], 1);
        g_tok[i2 * NTOK + s2] = token;
        g_cw[i2 * NTOK + s2]  = p2;
        g_sE[2 * token] = i1;  g_sP[2 * token] = s1;
        g_sE[2 * token + 1] = i2;  g_sP[2 * token + 1] = s2;
    }
}

// ---------------- tile scheduler (inline prefix: also returns expert offset) ----------------
__device__ __forceinline__ bool find_tile(int bx, int& e, int& tile, int& cnt, int& offs) {
    int acc = 0, off = 0;
    e = -1;
#pragma unroll
    for (int ee = 0; ee < NE; ee++) {
        int c = g_counts[ee];
        int t = (c + 127) >> 7;
        if (e < 0 && bx < acc + t) { e = ee; tile = bx - acc; cnt = c; offs = off; }
        acc += t;
        off += c;
    }
    return e >= 0;
}

// dynamic SMEM: [0:512) stok, [512:1024) scw, stages at 1024 + s*32768
#define STG_BASE 1024
#define STG_SZ   32768
#define SMEM_BYTES (STG_BASE + 3 * STG_SZ)

// ---------------- kernel 3: GEMM1 (x@w1^T, x@w3^T) -> silu*mul -> H(fp16) ----------------
__global__ __launch_bounds__(128, 2) void gemm1_kernel() {
    extern __shared__ char dsm[];
    int e, tile, cnt, offs;
    if (!find_tile(blockIdx.x, e, tile, cnt, offs)) return;
    int n0 = blockIdx.y * 64;

    int tid = threadIdx.x;
    int* stok = (int*)dsm;
    {
        int i = tile * 128 + tid;
        stok[tid] = (i < cnt) ? g_tok[e * NTOK + i] : -1;
    }
    __syncthreads();

    int warp = tid >> 5, lane = tid & 31;
    int wm = warp >> 1, wn = warp & 1;
    uint32_t sb = smem_u32(dsm);

    // ---- cp.async assignments: A 128x8 chunks (8/thr), B1/B3 64x8 (4/thr each) ----
    const __half* asrc[8]; uint32_t asz[8], adst[8];
#pragma unroll
    for (int j = 0; j < 8; j++) {
        int idx = tid + j * 128;
        int r = idx >> 3, c = idx & 7;
        int t = stok[r];
        asrc[j] = g_xh + (size_t)(t < 0 ? 0 : t) * DIM + c * 8;
        asz[j]  = (t < 0) ? 0u : 16u;
        adst[j] = swb32(r, c);
    }
    const __half* b1src[4]; const __half* b3src[4]; uint32_t bdst[4];
#pragma unroll
    for (int j = 0; j < 4; j++) {
        int idx = tid + j * 128;
        int r = idx >> 3, c = idx & 7;
        b1src[j] = g_w1h + (size_t)e * FF * DIM + (size_t)(n0 + r) * DIM + c * 8;
        b3src[j] = g_w3h + (size_t)e * FF * DIM + (size_t)(n0 + r) * DIM + c * 8;
        bdst[j]  = swb32(r, c);
    }
    auto issue_stage = [&](int s, int kt) {
        uint32_t base = sb + STG_BASE + s * STG_SZ;
        int k0 = kt * 64;
#pragma unroll
        for (int j = 0; j < 8; j++) cpa16(base + adst[j], asrc[j] + k0, asz[j]);
#pragma unroll
        for (int j = 0; j < 4; j++) cpa16(base + 16384 + bdst[j], b1src[j] + k0, 16);
#pragma unroll
        for (int j = 0; j < 4; j++) cpa16(base + 24576 + bdst[j], b3src[j] + k0, 16);
    };

    // ---- ldmatrix fragment offsets ----
    int arow = (((lane >> 3) & 1) << 3) + (lane & 7);
    int acol = lane >> 4;
    int brow = (((lane >> 4) & 1) << 3) + (lane & 7);
    int bcol = (lane >> 3) & 1;
    uint32_t offA[4][4], offB[2][4];
#pragma unroll
    for (int mt = 0; mt < 4; mt++)
#pragma unroll
        for (int kki = 0; kki < 4; kki++)
            offA[mt][kki] = swb32(wm * 64 + mt * 16 + arow, kki * 2 + acol);
#pragma unroll
    for (int p = 0; p < 2; p++)
#pragma unroll
        for (int kki = 0; kki < 4; kki++)
            offB[p][kki] = swb32(wn * 32 + p * 16 + brow, kki * 2 + bcol);

    float acc1[4][4][4] = {};
    float acc3[4][4][4] = {};

    auto compute_stage = [&](int s) {
        uint32_t base = sb + STG_BASE + s * STG_SZ;
        uint32_t aA = base, aB1 = base + 16384, aB3 = base + 24576;
#pragma unroll
        for (int kki = 0; kki < 4; kki++) {
            uint32_t a[4][4];
#pragma unroll
            for (int mt = 0; mt < 4; mt++)
                LDSM4(a[mt][0], a[mt][1], a[mt][2], a[mt][3], aA + offA[mt][kki]);
#pragma unroll
            for (int p = 0; p < 2; p++) {
                uint32_t b1[4], b3[4];
                LDSM4(b1[0], b1[1], b1[2], b1[3], aB1 + offB[p][kki]);
                LDSM4(b3[0], b3[1], b3[2], b3[3], aB3 + offB[p][kki]);
#pragma unroll
                for (int mt = 0; mt < 4; mt++) {
                    mma16(acc1[mt][2 * p],     a[mt], &b1[0]);
                    mma16(acc1[mt][2 * p + 1], a[mt], &b1[2]);
                    mma16(acc3[mt][2 * p],     a[mt], &b3[0]);
                    mma16(acc3[mt][2 * p + 1], a[mt], &b3[2]);
                }
            }
        }
    };

    issue_stage(0, 0); CP_COMMIT();
    issue_stage(1, 1); CP_COMMIT();
#pragma unroll 1
    for (int kt = 0; kt < NKT1; kt++) {
        CP_WAIT1();
        __syncthreads();
        compute_stage(kt % 3);
        if (kt + 2 < NKT1) issue_stage((kt + 2) % 3, kt + 2);
        CP_COMMIT();
    }

    // epilogue: h = silu(s1) * s3 -> g_H (fp16, half2 stores)
#pragma unroll
    for (int mt = 0; mt < 4; mt++) {
#pragma unroll
        for (int nt = 0; nt < 4; nt++) {
            int r0 = wm * 64 + mt * 16 + (lane >> 2);
            int cc = wn * 32 + nt * 8 + ((lane & 3) << 1);
#pragma unroll
            for (int h8 = 0; h8 < 2; h8++) {
                int i = tile * 128 + r0 + h8 * 8;
                if (i < cnt) {
                    float s1a = acc1[mt][nt][2 * h8],     s3a = acc3[mt][nt][2 * h8];
                    float s1b = acc1[mt][nt][2 * h8 + 1], s3b = acc3[mt][nt][2 * h8 + 1];
                    float ha = (s1a / (1.0f + __expf(-s1a))) * s3a;
                    float hb = (s1b / (1.0f + __expf(-s1b))) * s3b;
                    *(__half2*)(g_H + (size_t)(offs + i) * FF + n0 + cc) =
                        __floats2half2_rn(ha, hb);
                }
            }
        }
    }
}

// ---------------- kernel 4: GEMM2 (H @ w2^T), scaled rows -> g_O (no atomics) ----------------
__global__ __launch_bounds__(128, 2) void gemm2_kernel() {
    extern __shared__ char dsm[];
    int e, tile, cnt, offs;
    if (!find_tile(blockIdx.x, e, tile, cnt, offs)) return;
    int n0 = blockIdx.y * 128;

    int tid = threadIdx.x;
    float* scw = (float*)(dsm + 512);
    {
        int i = tile * 128 + tid;
        scw[tid] = (i < cnt) ? g_cw[e * NTOK + i] : 0.0f;
    }
    __syncthreads();

    int warp = tid >> 5, lane = tid & 31;
    int wm = warp >> 1, wn = warp & 1;
    uint32_t sb = smem_u32(dsm);

    const __half* asrc[8]; uint32_t asz[8], adst[8];
    const __half* bsrc[8];
#pragma unroll
    for (int j = 0; j < 8; j++) {
        int idx = tid + j * 128;
        int r = idx >> 3, c = idx & 7;
        bool av = (tile * 128 + r) < cnt;
        asrc[j] = g_H + (size_t)(offs + tile * 128 + (av ? r : 0)) * FF + c * 8;
        asz[j]  = av ? 16u : 0u;
        adst[j] = swb32(r, c);
        bsrc[j] = g_w2h + (size_t)e * DIM * FF + (size_t)(n0 + r) * FF + c * 8;
    }
    auto issue_stage = [&](int s, int kt) {
        uint32_t base = sb + STG_BASE + s * STG_SZ;
        int k0 = kt * 64;
#pragma unroll
        for (int j = 0; j < 8; j++) cpa16(base + adst[j], asrc[j] + k0, asz[j]);
#pragma unroll
        for (int j = 0; j < 8; j++) cpa16(base + 16384 + adst[j], bsrc[j] + k0, 16);
    };

    int arow = (((lane >> 3) & 1) << 3) + (lane & 7);
    int acol = lane >> 4;
    int brow = (((lane >> 4) & 1) << 3) + (lane & 7);
    int bcol = (lane >> 3) & 1;
    uint32_t offA[4][4], offB[4][4];
#pragma unroll
    for (int mt = 0; mt < 4; mt++)
#pragma unroll
        for (int kki = 0; kki < 4; kki++)
            offA[mt][kki] = swb32(wm * 64 + mt * 16 + arow, kki * 2 + acol);
#pragma unroll
    for (int p = 0; p < 4; p++)
#pragma unroll
        for (int kki = 0; kki < 4; kki++)
            offB[p][kki] = swb32(wn * 64 + p * 16 + brow, kki * 2 + bcol);

    float acc[4][8][4] = {};

    auto compute_stage = [&](int s) {
        uint32_t base = sb + STG_BASE + s * STG_SZ;
        uint32_t aA = base, aB = base + 16384;
#pragma unroll
        for (int kki = 0; kki < 4; kki++) {
            uint32_t a[4][4];
#pragma unroll
            for (int mt = 0; mt < 4; mt++)
                LDSM4(a[mt][0], a[mt][1], a[mt][2], a[mt][3], aA + offA[mt][kki]);
#pragma unroll
            for (int p = 0; p < 4; p++) {
                uint32_t b[4];
                LDSM4(b[0], b[1], b[2], b[3], aB + offB[p][kki]);
#pragma unroll
                for (int mt = 0; mt < 4; mt++) {
                    mma16(acc[mt][2 * p],     a[mt], &b[0]);
                    mma16(acc[mt][2 * p + 1], a[mt], &b[2]);
                }
            }
        }
    };

    issue_stage(0, 0); CP_COMMIT();
    issue_stage(1, 1); CP_COMMIT();
#pragma unroll 1
    for (int kt = 0; kt < NKT2; kt++) {
        CP_WAIT1();
        __syncthreads();
        compute_stage(kt % 3);
        if (kt + 2 < NKT2) issue_stage((kt + 2) % 3, kt + 2);
        CP_COMMIT();
    }

    // epilogue: g_O[slot row] = cw * acc  (plain stores, float2)
#pragma unroll
    for (int mt = 0; mt < 4; mt++) {
#pragma unroll
        for (int nt = 0; nt < 8; nt++) {
            int r0 = wm * 64 + mt * 16 + (lane >> 2);
            int cc = wn * 64 + nt * 8 + ((lane & 3) << 1);
#pragma unroll
            for (int h8 = 0; h8 < 2; h8++) {
                int r = r0 + h8 * 8;
                int i = tile * 128 + r;
                if (i < cnt) {
                    float w = scw[r];
                    float2 v = make_float2(acc[mt][nt][2 * h8] * w,
                                           acc[mt][nt][2 * h8 + 1] * w);
                    *(float2*)(g_O + (size_t)(offs + i) * DIM + n0 + cc) = v;
                }
            }
        }
    }
}

// ---------------- kernel 5: combine (one block per token, write-once out) ----------------
__global__ __launch_bounds__(256) void combine_kernel(float4* __restrict__ out) {
    __shared__ int soff[NE];
    if (threadIdx.x == 0) {
        int a = 0;
        for (int e = 0; e < NE; e++) { soff[e] = a; a += g_counts[e]; }
    }
    __syncthreads();
    int t = blockIdx.x;
    int d = threadIdx.x;                       // 256 float4 = 1024 floats
    size_t r1 = (size_t)(soff[g_sE[2 * t]]     + g_sP[2 * t]);
    size_t r2 = (size_t)(soff[g_sE[2 * t + 1]] + g_sP[2 * t + 1]);
    float4 a = ((const float4*)(g_O + r1 * DIM))[d];
    float4 b = ((const float4*)(g_O + r2 * DIM))[d];
    out[(size_t)t * (DIM / 4) + d] =
        make_float4(a.x + b.x, a.y + b.y, a.z + b.z, a.w + b.w);
}

// ---------------- launch (single stream, allocation-free) ----------------
extern "C" void kernel_launch(void* const* d_in, const int* in_sizes, int n_in,
                              void* d_out, int out_size) {
    const float* x  = (const float*)d_in[0];
    const float* gw = (const float*)d_in[1];
    const float* w1 = (const float*)d_in[2];
    const float* w2 = (const float*)d_in[3];
    const float* w3 = (const float*)d_in[4];
    float* out = (float*)d_out;

    cudaFuncSetAttribute(gemm1_kernel, cudaFuncAttributeMaxDynamicSharedMemorySize, SMEM_BYTES);
    cudaFuncSetAttribute(gemm2_kernel, cudaFuncAttributeMaxDynamicSharedMemorySize, SMEM_BYTES);

    __half *w1h, *w2h, *w3h;
    cudaGetSymbolAddress((void**)&w1h, g_w1h);
    cudaGetSymbolAddress((void**)&w2h, g_w2h);
    cudaGetSymbolAddress((void**)&w3h, g_w3h);

    int nw8 = NE * FF * DIM / 8;
    tohalf_kernel<<<(nw8 + 255) / 256, 256>>>(w1, w1h, nw8);
    tohalf_kernel<<<(nw8 + 255) / 256, 256>>>(w3, w3h, nw8);
    tohalf_kernel<<<(nw8 + 255) / 256, 256>>>(w2, w2h, nw8);

    init_kernel<<<1, 32>>>();
    gate_kernel<<<NTOK / 8, 256>>>(x, gw);                       // also x -> fp16

    gemm1_kernel<<<dim3(264, FF / 64), 128, SMEM_BYTES>>>();
    gemm2_kernel<<<dim3(264, DIM / 128), 128, SMEM_BYTES>>>();
    combine_kernel<<<NTOK, 256>>>((float4*)out);
}

// round 16
// speedup vs baseline: 1.5299x; 1.0248x over previous
#include <cuda_runtime.h>
#include <cuda_fp16.h>
#include <cstdint>
#include <math.h>

#define NE 8
#define NTOK 16384
#define DIM 1024
#define FF 2048
#define NKT1 (DIM / 64)
#define NKT2 (FF / 64)

// ---------------- scratch (device globals; no allocation) ----------------
__device__ int    g_counts[NE];
__device__ int    g_tok[NE * NTOK];
__device__ float  g_cw[NE * NTOK];
__device__ int    g_sE[2 * NTOK];                    // per-token expert of slot 0/1
__device__ int    g_sP[2 * NTOK];                    // per-token position within expert bucket
__device__ __half g_H[(size_t)2 * NTOK * FF];        // hidden activations (fp16)
__device__ float  g_O[(size_t)2 * NTOK * DIM];       // per-slot scaled expert outputs (fp32)
__device__ __half g_xh[(size_t)NTOK * DIM];          // fp16 x
__device__ __half g_w1h[(size_t)NE * FF * DIM];      // fp16 w1
__device__ __half g_w2h[(size_t)NE * DIM * FF];      // fp16 w2
__device__ __half g_w3h[(size_t)NE * FF * DIM];      // fp16 w3

// ---------------- helpers ----------------
__device__ __forceinline__ uint32_t ph2(float a, float b) {
    __half2 h = __floats2half2_rn(a, b);
    return *(uint32_t*)&h;
}

static __device__ __forceinline__ uint32_t smem_u32(const void* p) {
    uint32_t a;
    asm("{ .reg .u64 t; cvta.to.shared.u64 t, %1; cvt.u32.u64 %0, t; }" : "=r"(a) : "l"(p));
    return a;
}

__device__ __forceinline__ void mma16(float* c, const uint32_t* a, const uint32_t* b) {
    asm volatile(
        "mma.sync.aligned.m16n8k16.row.col.f32.f16.f16.f32 "
        "{%0,%1,%2,%3},{%4,%5,%6,%7},{%8,%9},{%0,%1,%2,%3};"
        : "+f"(c[0]), "+f"(c[1]), "+f"(c[2]), "+f"(c[3])
        : "r"(a[0]), "r"(a[1]), "r"(a[2]), "r"(a[3]), "r"(b[0]), "r"(b[1]));
}

#define LDSM4(r0_, r1_, r2_, r3_, addr)                                        \
    asm volatile("ldmatrix.sync.aligned.m8n8.x4.shared.b16 {%0,%1,%2,%3}, [%4];" \
        : "=r"(r0_), "=r"(r1_), "=r"(r2_), "=r"(r3_) : "r"(addr))

__device__ __forceinline__ void cpa16(uint32_t dst, const void* src, uint32_t nbytes) {
    asm volatile("cp.async.cg.shared.global [%0], [%1], 16, %2;"
                 :: "r"(dst), "l"(src), "r"(nbytes) : "memory");
}
#define CP_COMMIT() asm volatile("cp.async.commit_group;" ::: "memory")
#define CP_WAIT1()  asm volatile("cp.async.wait_group 1;" ::: "memory")

// 128B-row swizzle (64 halfs/row): row r, 16B chunk c (0..7) -> phys chunk c^(r&7).
__device__ __forceinline__ uint32_t swb32(int r, int c) {
    return (uint32_t)(r * 128 + ((c ^ r) & 7) * 16);
}

// ---------------- prepass: all 3 weights fp32 -> fp16 in one launch (+count init) ----------------
__global__ void tohalf3_kernel(const float* __restrict__ w1,
                               const float* __restrict__ w2,
                               const float* __restrict__ w3, int n8) {
    if (blockIdx.x == 0 && blockIdx.y == 0 && threadIdx.x < NE)
        g_counts[threadIdx.x] = 0;
    int i = blockIdx.x * blockDim.x + threadIdx.x;
    if (i >= n8) return;
    const float* src = (blockIdx.y == 0) ? w1 : (blockIdx.y == 1) ? w2 : w3;
    __half* dst = (blockIdx.y == 0) ? g_w1h : (blockIdx.y == 1) ? g_w2h : g_w3h;
    float4 a = ((const float4*)src)[2 * i];
    float4 b = ((const float4*)src)[2 * i + 1];
    uint4 u;
    u.x = ph2(a.x, a.y); u.y = ph2(a.z, a.w);
    u.z = ph2(b.x, b.y); u.w = ph2(b.z, b.w);
    ((uint4*)dst)[i] = u;
}

// ---------------- kernel 1: gating + routing + x->fp16 (one warp per token) ----------------
__global__ void gate_kernel(const float* __restrict__ x, const float* __restrict__ gw) {
    int warp = threadIdx.x >> 5;
    int lane = threadIdx.x & 31;
    int token = blockIdx.x * 8 + warp;

    const float* xr = x + (size_t)token * DIM;
    float xv[32];
#pragma unroll
    for (int j = 0; j < 32; j++) xv[j] = xr[j * 32 + lane];

    __half* xh = g_xh + (size_t)token * DIM;
#pragma unroll
    for (int j = 0; j < 32; j++) xh[j * 32 + lane] = __float2half_rn(xv[j]);

    float logits[NE];
#pragma unroll
    for (int e = 0; e < NE; e++) {
        const float* g = gw + e * DIM;
        float s = 0.0f;
#pragma unroll
        for (int j = 0; j < 32; j++) s += xv[j] * g[j * 32 + lane];
#pragma unroll
        for (int o = 16; o; o >>= 1) s += __shfl_xor_sync(0xffffffffu, s, o);
        logits[e] = s;
    }

    if (lane == 0) {
        int i1 = 0;
#pragma unroll
        for (int e = 1; e < NE; e++)
            if (logits[e] > logits[i1]) i1 = e;
        int i2 = -1;
#pragma unroll
        for (int e = 0; e < NE; e++) {
            if (e == i1) continue;
            if (i2 < 0 || logits[e] > logits[i2]) i2 = e;
        }
        float p1 = 1.0f / (1.0f + __expf(logits[i2] - logits[i1]));
        float p2 = 1.0f - p1;
        int s1 = atomicAdd(&g_counts[i1], 1);
        g_tok[i1 * NTOK + s1] = token;
        g_cw[i1 * NTOK + s1]  = p1;
        int s2 = atomicAdd(&g_counts[i2], 1);
        g_tok[i2 * NTOK + s2] = token;
        g_cw[i2 * NTOK + s2]  = p2;
        g_sE[2 * token] = i1;  g_sP[2 * token] = s1;
        g_sE[2 * token + 1] = i2;  g_sP[2 * token + 1] = s2;
    }
}

// ---------------- tile scheduler (inline prefix: also returns expert offset) ----------------
__device__ __forceinline__ bool find_tile(int bx, int& e, int& tile, int& cnt, int& offs) {
    int acc = 0, off = 0;
    e = -1;
#pragma unroll
    for (int ee = 0; ee < NE; ee++) {
        int c = g_counts[ee];
        int t = (c + 127) >> 7;
        if (e < 0 && bx < acc + t) { e = ee; tile = bx - acc; cnt = c; offs = off; }
        acc += t;
        off += c;
    }
    return e >= 0;
}

// dynamic SMEM: [0:512) stok, [512:1024) scw, stages at 1024 + s*32768
#define STG_BASE 1024
#define STG_SZ   32768
#define SMEM_BYTES (STG_BASE + 3 * STG_SZ)

// ---------------- kernel 3: GEMM1 (x@w1^T, x@w3^T) -> silu*mul -> H(fp16) ----------------
__global__ __launch_bounds__(128, 2) void gemm1_kernel() {
    extern __shared__ char dsm[];
    int e, tile, cnt, offs;
    if (!find_tile(blockIdx.x, e, tile, cnt, offs)) return;
    int n0 = blockIdx.y * 64;

    int tid = threadIdx.x;
    int* stok = (int*)dsm;
    {
        int i = tile * 128 + tid;
        stok[tid] = (i < cnt) ? g_tok[e * NTOK + i] : -1;
    }
    __syncthreads();

    int warp = tid >> 5, lane = tid & 31;
    int wm = warp >> 1, wn = warp & 1;
    uint32_t sb = smem_u32(dsm);

    // ---- cp.async assignments: A 128x8 chunks (8/thr), B1/B3 64x8 (4/thr each) ----
    const __half* asrc[8]; uint32_t asz[8], adst[8];
#pragma unroll
    for (int j = 0; j < 8; j++) {
        int idx = tid + j * 128;
        int r = idx >> 3, c = idx & 7;
        int t = stok[r];
        asrc[j] = g_xh + (size_t)(t < 0 ? 0 : t) * DIM + c * 8;
        asz[j]  = (t < 0) ? 0u : 16u;
        adst[j] = swb32(r, c);
    }
    const __half* b1src[4]; const __half* b3src[4]; uint32_t bdst[4];
#pragma unroll
    for (int j = 0; j < 4; j++) {
        int idx = tid + j * 128;
        int r = idx >> 3, c = idx & 7;
        b1src[j] = g_w1h + (size_t)e * FF * DIM + (size_t)(n0 + r) * DIM + c * 8;
        b3src[j] = g_w3h + (size_t)e * FF * DIM + (size_t)(n0 + r) * DIM + c * 8;
        bdst[j]  = swb32(r, c);
    }
    auto issue_stage = [&](int s, int kt) {
        uint32_t base = sb + STG_BASE + s * STG_SZ;
        int k0 = kt * 64;
#pragma unroll
        for (int j = 0; j < 8; j++) cpa16(base + adst[j], asrc[j] + k0, asz[j]);
#pragma unroll
        for (int j = 0; j < 4; j++) cpa16(base + 16384 + bdst[j], b1src[j] + k0, 16);
#pragma unroll
        for (int j = 0; j < 4; j++) cpa16(base + 24576 + bdst[j], b3src[j] + k0, 16);
    };

    // ---- ldmatrix fragment offsets ----
    int arow = (((lane >> 3) & 1) << 3) + (lane & 7);
    int acol = lane >> 4;
    int brow = (((lane >> 4) & 1) << 3) + (lane & 7);
    int bcol = (lane >> 3) & 1;
    uint32_t offA[4][4], offB[2][4];
#pragma unroll
    for (int mt = 0; mt < 4; mt++)
#pragma unroll
        for (int kki = 0; kki < 4; kki++)
            offA[mt][kki] = swb32(wm * 64 + mt * 16 + arow, kki * 2 + acol);
#pragma unroll
    for (int p = 0; p < 2; p++)
#pragma unroll
        for (int kki = 0; kki < 4; kki++)
            offB[p][kki] = swb32(wn * 32 + p * 16 + brow, kki * 2 + bcol);

    float acc1[4][4][4] = {};
    float acc3[4][4][4] = {};

    // software-pipelined compute: load kki+1 fragments during kki MMAs
    auto compute_stage = [&](int s) {
        uint32_t base = sb + STG_BASE + s * STG_SZ;
        uint32_t aA = base, aB1 = base + 16384, aB3 = base + 24576;
        uint32_t a[2][4][4], b1f[2][2][4], b3f[2][2][4];
        auto ldk = [&](int buf, int kki) {
#pragma unroll
            for (int mt = 0; mt < 4; mt++)
                LDSM4(a[buf][mt][0], a[buf][mt][1], a[buf][mt][2], a[buf][mt][3],
                      aA + offA[mt][kki]);
#pragma unroll
            for (int p = 0; p < 2; p++) {
                LDSM4(b1f[buf][p][0], b1f[buf][p][1], b1f[buf][p][2], b1f[buf][p][3],
                      aB1 + offB[p][kki]);
                LDSM4(b3f[buf][p][0], b3f[buf][p][1], b3f[buf][p][2], b3f[buf][p][3],
                      aB3 + offB[p][kki]);
            }
        };
        ldk(0, 0);
#pragma unroll
        for (int kki = 0; kki < 4; kki++) {
            int cur = kki & 1;
            if (kki < 3) ldk(cur ^ 1, kki + 1);
#pragma unroll
            for (int p = 0; p < 2; p++) {
#pragma unroll
                for (int mt = 0; mt < 4; mt++) {
                    mma16(acc1[mt][2 * p],     a[cur][mt], &b1f[cur][p][0]);
                    mma16(acc1[mt][2 * p + 1], a[cur][mt], &b1f[cur][p][2]);
                    mma16(acc3[mt][2 * p],     a[cur][mt], &b3f[cur][p][0]);
                    mma16(acc3[mt][2 * p + 1], a[cur][mt], &b3f[cur][p][2]);
                }
            }
        }
    };

    issue_stage(0, 0); CP_COMMIT();
    issue_stage(1, 1); CP_COMMIT();
#pragma unroll 1
    for (int kt = 0; kt < NKT1; kt++) {
        CP_WAIT1();
        __syncthreads();
        compute_stage(kt % 3);
        if (kt + 2 < NKT1) issue_stage((kt + 2) % 3, kt + 2);
        CP_COMMIT();
    }

    // epilogue: h = silu(s1) * s3 -> g_H (fp16, half2 stores)
#pragma unroll
    for (int mt = 0; mt < 4; mt++) {
#pragma unroll
        for (int nt = 0; nt < 4; nt++) {
            int r0 = wm * 64 + mt * 16 + (lane >> 2);
            int cc = wn * 32 + nt * 8 + ((lane & 3) << 1);
#pragma unroll
            for (int h8 = 0; h8 < 2; h8++) {
                int i = tile * 128 + r0 + h8 * 8;
                if (i < cnt) {
                    float s1a = acc1[mt][nt][2 * h8],     s3a = acc3[mt][nt][2 * h8];
                    float s1b = acc1[mt][nt][2 * h8 + 1], s3b = acc3[mt][nt][2 * h8 + 1];
                    float ha = (s1a / (1.0f + __expf(-s1a))) * s3a;
                    float hb = (s1b / (1.0f + __expf(-s1b))) * s3b;
                    *(__half2*)(g_H + (size_t)(offs + i) * FF + n0 + cc) =
                        __floats2half2_rn(ha, hb);
                }
            }
        }
    }
}

// ---------------- kernel 4: GEMM2 (H @ w2^T), scaled rows -> g_O (no atomics) ----------------
__global__ __launch_bounds__(128, 2) void gemm2_kernel() {
    extern __shared__ char dsm[];
    int e, tile, cnt, offs;
    if (!find_tile(blockIdx.x, e, tile, cnt, offs)) return;
    int n0 = blockIdx.y * 128;

    int tid = threadIdx.x;
    float* scw = (float*)(dsm + 512);
    {
        int i = tile * 128 + tid;
        scw[tid] = (i < cnt) ? g_cw[e * NTOK + i] : 0.0f;
    }
    __syncthreads();

    int warp = tid >> 5, lane = tid & 31;
    int wm = warp >> 1, wn = warp & 1;
    uint32_t sb = smem_u32(dsm);

    const __half* asrc[8]; uint32_t asz[8], adst[8];
    const __half* bsrc[8];
#pragma unroll
    for (int j = 0; j < 8; j++) {
        int idx = tid + j * 128;
        int r = idx >> 3, c = idx & 7;
        bool av = (tile * 128 + r) < cnt;
        asrc[j] = g_H + (size_t)(offs + tile * 128 + (av ? r : 0)) * FF + c * 8;
        asz[j]  = av ? 16u : 0u;
        adst[j] = swb32(r, c);
        bsrc[j] = g_w2h + (size_t)e * DIM * FF + (size_t)(n0 + r) * FF + c * 8;
    }
    auto issue_stage = [&](int s, int kt) {
        uint32_t base = sb + STG_BASE + s * STG_SZ;
        int k0 = kt * 64;
#pragma unroll
        for (int j = 0; j < 8; j++) cpa16(base + adst[j], asrc[j] + k0, asz[j]);
#pragma unroll
        for (int j = 0; j < 8; j++) cpa16(base + 16384 + adst[j], bsrc[j] + k0, 16);
    };

    int arow = (((lane >> 3) & 1) << 3) + (lane & 7);
    int acol = lane >> 4;
    int brow = (((lane >> 4) & 1) << 3) + (lane & 7);
    int bcol = (lane >> 3) & 1;
    uint32_t offA[4][4], offB[4][4];
#pragma unroll
    for (int mt = 0; mt < 4; mt++)
#pragma unroll
        for (int kki = 0; kki < 4; kki++)
            offA[mt][kki] = swb32(wm * 64 + mt * 16 + arow, kki * 2 + acol);
#pragma unroll
    for (int p = 0; p < 4; p++)
#pragma unroll
        for (int kki = 0; kki < 4; kki++)
            offB[p][kki] = swb32(wn * 64 + p * 16 + brow, kki * 2 + bcol);

    float acc[4][8][4] = {};

    auto compute_stage = [&](int s) {
        uint32_t base = sb + STG_BASE + s * STG_SZ;
        uint32_t aA = base, aB = base + 16384;
        uint32_t a[2][4][4], bf[2][4][4];
        auto ldk = [&](int buf, int kki) {
#pragma unroll
            for (int mt = 0; mt < 4; mt++)
                LDSM4(a[buf][mt][0], a[buf][mt][1], a[buf][mt][2], a[buf][mt][3],
                      aA + offA[mt][kki]);
#pragma unroll
            for (int p = 0; p < 4; p++)
                LDSM4(bf[buf][p][0], bf[buf][p][1], bf[buf][p][2], bf[buf][p][3],
                      aB + offB[p][kki]);
        };
        ldk(0, 0);
#pragma unroll
        for (int kki = 0; kki < 4; kki++) {
            int cur = kki & 1;
            if (kki < 3) ldk(cur ^ 1, kki + 1);
#pragma unroll
            for (int p = 0; p < 4; p++) {
#pragma unroll
                for (int mt = 0; mt < 4; mt++) {
                    mma16(acc[mt][2 * p],     a[cur][mt], &bf[cur][p][0]);
                    mma16(acc[mt][2 * p + 1], a[cur][mt], &bf[cur][p][2]);
                }
            }
        }
    };

    issue_stage(0, 0); CP_COMMIT();
    issue_stage(1, 1); CP_COMMIT();
#pragma unroll 1
    for (int kt = 0; kt < NKT2; kt++) {
        CP_WAIT1();
        __syncthreads();
        compute_stage(kt % 3);
        if (kt + 2 < NKT2) issue_stage((kt + 2) % 3, kt + 2);
        CP_COMMIT();
    }

    // epilogue: g_O[slot row] = cw * acc  (plain stores, float2)
#pragma unroll
    for (int mt = 0; mt < 4; mt++) {
#pragma unroll
        for (int nt = 0; nt < 8; nt++) {
            int r0 = wm * 64 + mt * 16 + (lane >> 2);
            int cc = wn * 64 + nt * 8 + ((lane & 3) << 1);
#pragma unroll
            for (int h8 = 0; h8 < 2; h8++) {
                int r = r0 + h8 * 8;
                int i = tile * 128 + r;
                if (i < cnt) {
                    float w = scw[r];
                    float2 v = make_float2(acc[mt][nt][2 * h8] * w,
                                           acc[mt][nt][2 * h8 + 1] * w);
                    *(float2*)(g_O + (size_t)(offs + i) * DIM + n0 + cc) = v;
                }
            }
        }
    }
}

// ---------------- kernel 5: combine (one block per token, write-once out) ----------------
__global__ __launch_bounds__(256) void combine_kernel(float4* __restrict__ out) {
    __shared__ int soff[NE];
    if (threadIdx.x == 0) {
        int a = 0;
        for (int e = 0; e < NE; e++) { soff[e] = a; a += g_counts[e]; }
    }
    __syncthreads();
    int t = blockIdx.x;
    int d = threadIdx.x;
    size_t r1 = (size_t)(soff[g_sE[2 * t]]     + g_sP[2 * t]);
    size_t r2 = (size_t)(soff[g_sE[2 * t + 1]] + g_sP[2 * t + 1]);
    float4 a = ((const float4*)(g_O + r1 * DIM))[d];
    float4 b = ((const float4*)(g_O + r2 * DIM))[d];
    out[(size_t)t * (DIM / 4) + d] =
        make_float4(a.x + b.x, a.y + b.y, a.z + b.z, a.w + b.w);
}

// ---------------- launch (single stream, allocation-free, 5 launches) ----------------
extern "C" void kernel_launch(void* const* d_in, const int* in_sizes, int n_in,
                              void* d_out, int out_size) {
    const float* x  = (const float*)d_in[0];
    const float* gw = (const float*)d_in[1];
    const float* w1 = (const float*)d_in[2];
    const float* w2 = (const float*)d_in[3];
    const float* w3 = (const float*)d_in[4];
    float* out = (float*)d_out;

    cudaFuncSetAttribute(gemm1_kernel, cudaFuncAttributeMaxDynamicSharedMemorySize, SMEM_BYTES);
    cudaFuncSetAttribute(gemm2_kernel, cudaFuncAttributeMaxDynamicSharedMemorySize, SMEM_BYTES);

    int nw8 = NE * FF * DIM / 8;
    tohalf3_kernel<<<dim3((nw8 + 255) / 256, 3), 256>>>(w1, w2, w3, nw8);
    gate_kernel<<<NTOK / 8, 256>>>(x, gw);                       // also x -> fp16

    gemm1_kernel<<<dim3(264, FF / 64), 128, SMEM_BYTES>>>();
    gemm2_kernel<<<dim3(264, DIM / 128), 128, SMEM_BYTES>>>();
    combine_kernel<<<NTOK, 256>>>((float4*)out);
}